// round 10
// baseline (speedup 1.0000x reference)
#include <cuda_runtime.h>
#include <cuda_bf16.h>
#include <cstdint>

#define NB 16
#define NN 1024
#define NELEM ((size_t)NB * NN * NN)

// ---------------------------------------------------------------------------
// Scratch (device globals — allocation-free)
// ---------------------------------------------------------------------------
__device__ float          g_scores[NELEM];                 // fp32 scores S
__device__ __nv_bfloat16  g_q0[NELEM], g_q1[NELEM];        // Q split
__device__ __nv_bfloat16  g_e0[NELEM], g_e1[NELEM];        // E split (row-major)
__device__ __nv_bfloat16  g_e0t[NELEM], g_e1t[NELEM];      // E split transposed
__device__ __nv_bfloat16  g_p0[NELEM], g_p1[NELEM];        // softmax probs split

// ---------------------------------------------------------------------------
// PTX helpers (sm_80-era ISA only: mma.sync / ldmatrix / cp.async)
// ---------------------------------------------------------------------------
__device__ __forceinline__ uint32_t smem_u32(const void* p) {
    return (uint32_t)__cvta_generic_to_shared(p);
}
__device__ __forceinline__ void cp16(uint32_t saddr, const void* g) {
    asm volatile("cp.async.cg.shared.global [%0], [%1], 16;" :: "r"(saddr), "l"(g));
}
#define CP_COMMIT()  asm volatile("cp.async.commit_group;" ::: "memory")
#define CP_WAIT1()   asm volatile("cp.async.wait_group 1;" ::: "memory")

#define LDSM4(r, addr) \
    asm volatile("ldmatrix.sync.aligned.m8n8.x4.shared.b16 {%0,%1,%2,%3}, [%4];" \
        : "=r"((r)[0]), "=r"((r)[1]), "=r"((r)[2]), "=r"((r)[3]) : "r"(addr))

#define MMA16816(d, a, b) \
    asm volatile("mma.sync.aligned.m16n8k16.row.col.f32.bf16.bf16.f32 " \
        "{%0,%1,%2,%3}, {%4,%5,%6,%7}, {%8,%9}, {%0,%1,%2,%3};" \
        : "+f"((d)[0]), "+f"((d)[1]), "+f"((d)[2]), "+f"((d)[3]) \
        : "r"((a)[0]), "r"((a)[1]), "r"((a)[2]), "r"((a)[3]), \
          "r"((b)[0]), "r"((b)[1]))

// ---------------------------------------------------------------------------
// fp32 -> 2-term bf16 split (which=0: Q->q0,q1 ; which=1: E->e0,e1)
// ---------------------------------------------------------------------------
__global__ __launch_bounds__(256) void split_kernel(const float* __restrict__ x, int which)
{
    size_t i = ((size_t)blockIdx.x * 256 + threadIdx.x) * 8;
    float4 a = *(const float4*)(x + i);
    float4 b = *(const float4*)(x + i + 4);
    float v[8] = {a.x, a.y, a.z, a.w, b.x, b.y, b.z, b.w};
    __nv_bfloat16 h0[8], h1[8];
#pragma unroll
    for (int j = 0; j < 8; j++) {
        h0[j] = __float2bfloat16(v[j]);
        h1[j] = __float2bfloat16(v[j] - __bfloat162float(h0[j]));
    }
    __nv_bfloat16* o0 = which ? g_e0 : g_q0;
    __nv_bfloat16* o1 = which ? g_e1 : g_q1;
    *(uint4*)(o0 + i) = *(const uint4*)h0;
    *(uint4*)(o1 + i) = *(const uint4*)h1;
}

// ---------------------------------------------------------------------------
// Transpose e0,e1 -> e0t,e1t  (per batch, 64x64 tiles)
// ---------------------------------------------------------------------------
__global__ __launch_bounds__(256) void transpose_kernel()
{
    __shared__ __nv_bfloat16 tile[64][72];
    const int bj = blockIdx.x, bi = blockIdx.y;
    const size_t boff = (size_t)blockIdx.z * NN * NN;
    const int t = threadIdx.x;

#pragma unroll
    for (int arr = 0; arr < 2; arr++) {
        const __nv_bfloat16* src = arr ? g_e1 : g_e0;
        __nv_bfloat16*       dst = arr ? g_e1t : g_e0t;
        if (arr) __syncthreads();
#pragma unroll
        for (int i = 0; i < 2; i++) {
            int v = t + i * 256;
            int r = v >> 3, j = v & 7;
            *(uint4*)&tile[r][j * 8] =
                *(const uint4*)(src + boff + (size_t)(bi * 64 + r) * NN + bj * 64 + j * 8);
        }
        __syncthreads();
#pragma unroll
        for (int i = 0; i < 2; i++) {
            int v = t + i * 256;
            int r = v >> 3, j = v & 7;
            __nv_bfloat16 out[8];
#pragma unroll
            for (int c = 0; c < 8; c++) out[c] = tile[j * 8 + c][r];
            *(uint4*)(dst + boff + (size_t)(bj * 64 + r) * NN + bi * 64 + j * 8) =
                *(const uint4*)out;
        }
    }
}

// ---------------------------------------------------------------------------
// HMMA GEMM (NT): C[128x128 tile] = A0·B0^T + A0·B1^T + A1·B0^T
//   mode 0: A=q0/q1, B=e0/e1, C=g_scores   (S = Q·E^T)
//   mode 1: A=p0/p1, B=e0t/e1t, C=Cout     (O = P·E)
// Operands K-major [rows x 1024] bf16. BK=32, 3-stage cp.async pipeline.
// 128 threads, 2x2 warp grid, 64x64 warp tile (MAC/LDSM-byte = 24).
// 96 KB smem -> 2 CTAs/SM; 128 regs budget is generous (256 thr/SM total).
// smem stage: A0 | A1 | B0 | B1, each 128x32 bf16 (64B rows, xor swizzle).
// ---------------------------------------------------------------------------
#define STAGE_BYTES 32768
#define GEMM_SMEM   (3 * STAGE_BYTES)

__global__ __launch_bounds__(128, 2) void gemm_kernel(float* __restrict__ Cout, int mode)
{
    extern __shared__ __align__(1024) char smem[];
    const uint32_t sbase = smem_u32(smem);

    const int t = threadIdx.x;
    const int lane = t & 31, w = t >> 5;
    const int wm = w >> 1, wn = w & 1;          // 2 x 2 warp grid, 64x64 warp tile

    const size_t boff = (size_t)blockIdx.z * NN * NN;
    const int m0 = blockIdx.y * 128, n0 = blockIdx.x * 128;

    const __nv_bfloat16* gsrc[4];
    gsrc[0] = (mode ? g_p0  : g_q0) + boff + (size_t)m0 * NN;   // A comp0
    gsrc[1] = (mode ? g_p1  : g_q1) + boff + (size_t)m0 * NN;   // A comp1
    gsrc[2] = (mode ? g_e0t : g_e0) + boff + (size_t)n0 * NN;   // B comp0
    gsrc[3] = (mode ? g_e1t : g_e1) + boff + (size_t)n0 * NN;   // B comp1
    float* Cb = (mode ? Cout : g_scores) + boff;

    // --- gmem->smem mapping: thread t owns row t of each tile (4 x 16B) ----
    const uint32_t srow = (uint32_t)t * 64;
    const uint32_t tl3 = (uint32_t)(t & 3);

    float acc[4][8][4];
#pragma unroll
    for (int i = 0; i < 4; i++)
#pragma unroll
        for (int j = 0; j < 8; j++)
#pragma unroll
            for (int r = 0; r < 4; r++) acc[i][j][r] = 0.f;

    // --- pipeline prologue: stages 0,1 --------------------------------------
#pragma unroll
    for (int s = 0; s < 2; s++) {
        const uint32_t sb = sbase + s * STAGE_BYTES;
        const size_t go = (size_t)s * 32 + (size_t)t * NN;
#pragma unroll
        for (int a = 0; a < 4; a++)
#pragma unroll
            for (int c = 0; c < 4; c++)
                cp16(sb + a * 8192 + srow + (((uint32_t)c ^ tl3) << 4),
                     gsrc[a] + go + c * 8);
        CP_COMMIT();
    }

    // --- ldmatrix per-lane offsets ------------------------------------------
    const uint32_t rowA = (uint32_t)(wm * 64 + (lane & 15));
    const uint32_t hiA  = (uint32_t)(lane >> 4);
    const uint32_t rowB = (uint32_t)(wn * 64 + ((lane >> 4) << 3) + (lane & 7));
    const uint32_t hiB  = (uint32_t)((lane >> 3) & 1);
    const uint32_t l3   = (uint32_t)(lane & 3);

    // --- mainloop: 32 iterations of BK=32 -----------------------------------
    int buf = 0;                                  // kt % 3
    int nbuf = 2;                                 // (kt+2) % 3
#pragma unroll 1
    for (int kt = 0; kt < 32; kt++) {
        CP_WAIT1();
        __syncthreads();

        // issue loads for stage kt+2 (buffer consumed at iter kt-1)
        if (kt < 30) {
            const uint32_t sb = sbase + nbuf * STAGE_BYTES;
            const size_t go = (size_t)(kt + 2) * 32 + (size_t)t * NN;
#pragma unroll
            for (int a = 0; a < 4; a++)
#pragma unroll
                for (int c = 0; c < 4; c++)
                    cp16(sb + a * 8192 + srow + (((uint32_t)c ^ tl3) << 4),
                         gsrc[a] + go + c * 8);
        }
        CP_COMMIT();

        const uint32_t base = sbase + buf * STAGE_BYTES;
#pragma unroll
        for (int ks = 0; ks < 2; ks++) {
            const uint32_t kb = (uint32_t)(ks * 2);
            uint32_t af[16], bf0[16], bf1[16];

            const uint32_t offA = rowA * 64 + (((kb + hiA) ^ l3) << 4);
            const uint32_t offB = rowB * 64 + (((kb + hiB) ^ l3) << 4);

            LDSM4(af,       base + offA);
            LDSM4(af + 4,   base + offA + 16 * 64);
            LDSM4(af + 8,   base + offA + 32 * 64);
            LDSM4(af + 12,  base + offA + 48 * 64);

            LDSM4(bf0,      base + 16384 + offB);
            LDSM4(bf0 + 4,  base + 16384 + offB + 16 * 64);
            LDSM4(bf0 + 8,  base + 16384 + offB + 32 * 64);
            LDSM4(bf0 + 12, base + 16384 + offB + 48 * 64);

            LDSM4(bf1,      base + 24576 + offB);
            LDSM4(bf1 + 4,  base + 24576 + offB + 16 * 64);
            LDSM4(bf1 + 8,  base + 24576 + offB + 32 * 64);
            LDSM4(bf1 + 12, base + 24576 + offB + 48 * 64);

            // A0·B0 and A0·B1
#pragma unroll
            for (int mt = 0; mt < 4; mt++)
#pragma unroll
                for (int nt = 0; nt < 8; nt++)
                    MMA16816(acc[mt][nt], af + mt * 4,
                             bf0 + (nt >> 1) * 4 + (nt & 1) * 2);
#pragma unroll
            for (int mt = 0; mt < 4; mt++)
#pragma unroll
                for (int nt = 0; nt < 8; nt++)
                    MMA16816(acc[mt][nt], af + mt * 4,
                             bf1 + (nt >> 1) * 4 + (nt & 1) * 2);

            // A comp1 reuses af registers
            LDSM4(af,       base + 8192 + offA);
            LDSM4(af + 4,   base + 8192 + offA + 16 * 64);
            LDSM4(af + 8,   base + 8192 + offA + 32 * 64);
            LDSM4(af + 12,  base + 8192 + offA + 48 * 64);
#pragma unroll
            for (int mt = 0; mt < 4; mt++)
#pragma unroll
                for (int nt = 0; nt < 8; nt++)
                    MMA16816(acc[mt][nt], af + mt * 4,
                             bf0 + (nt >> 1) * 4 + (nt & 1) * 2);
        }

        buf  = (buf  == 2) ? 0 : buf + 1;
        nbuf = (nbuf == 2) ? 0 : nbuf + 1;
    }

    // --- epilogue: direct fp32 stores ---------------------------------------
    const int er = lane >> 2, ec = (lane & 3) * 2;
#pragma unroll
    for (int mt = 0; mt < 4; mt++) {
        const int rr = m0 + wm * 64 + mt * 16 + er;
#pragma unroll
        for (int nt = 0; nt < 8; nt++) {
            const int cc = n0 + wn * 64 + nt * 8 + ec;
            *(float2*)&Cb[(size_t)rr * NN + cc] =
                make_float2(acc[mt][nt][0], acc[mt][nt][1]);
            *(float2*)&Cb[(size_t)(rr + 8) * NN + cc] =
                make_float2(acc[mt][nt][2], acc[mt][nt][3]);
        }
    }
}

// ---------------------------------------------------------------------------
// Row softmax over g_scores; writes 2-term bf16 split of probs to g_p0,g_p1
// ---------------------------------------------------------------------------
__global__ __launch_bounds__(128) void softmax_kernel()
{
    __shared__ float red[4];
    const size_t rowoff = (size_t)blockIdx.x * NN;
    const float* p = g_scores + rowoff;
    const int t = threadIdx.x, lane = t & 31, wid = t >> 5;

    float4 v0 = ((const float4*)p)[t];
    float4 v1 = ((const float4*)p)[t + 128];

    float m = fmaxf(fmaxf(fmaxf(v0.x, v0.y), fmaxf(v0.z, v0.w)),
                    fmaxf(fmaxf(v1.x, v1.y), fmaxf(v1.z, v1.w)));
#pragma unroll
    for (int off = 16; off > 0; off >>= 1)
        m = fmaxf(m, __shfl_xor_sync(0xffffffffu, m, off));
    if (lane == 0) red[wid] = m;
    __syncthreads();
    m = fmaxf(fmaxf(red[0], red[1]), fmaxf(red[2], red[3]));
    __syncthreads();

    v0.x = __expf(v0.x - m); v0.y = __expf(v0.y - m);
    v0.z = __expf(v0.z - m); v0.w = __expf(v0.w - m);
    v1.x = __expf(v1.x - m); v1.y = __expf(v1.y - m);
    v1.z = __expf(v1.z - m); v1.w = __expf(v1.w - m);

    float s = v0.x + v0.y + v0.z + v0.w + v1.x + v1.y + v1.z + v1.w;
#pragma unroll
    for (int off = 16; off > 0; off >>= 1)
        s += __shfl_xor_sync(0xffffffffu, s, off);
    if (lane == 0) red[wid] = s;
    __syncthreads();
    s = red[0] + red[1] + red[2] + red[3];
    const float inv = 1.0f / s;

    float w0[4] = {v0.x * inv, v0.y * inv, v0.z * inv, v0.w * inv};
    float w1[4] = {v1.x * inv, v1.y * inv, v1.z * inv, v1.w * inv};

    __nv_bfloat16 a0[4], a1[4], b0[4], b1[4];
#pragma unroll
    for (int j = 0; j < 4; j++) {
        a0[j] = __float2bfloat16(w0[j]);
        a1[j] = __float2bfloat16(w0[j] - __bfloat162float(a0[j]));
        b0[j] = __float2bfloat16(w1[j]);
        b1[j] = __float2bfloat16(w1[j] - __bfloat162float(b0[j]));
    }
    *(uint2*)(g_p0 + rowoff + t * 4)       = *(const uint2*)a0;
    *(uint2*)(g_p1 + rowoff + t * 4)       = *(const uint2*)a1;
    *(uint2*)(g_p0 + rowoff + 512 + t * 4) = *(const uint2*)b0;
    *(uint2*)(g_p1 + rowoff + 512 + t * 4) = *(const uint2*)b1;
}

// ---------------------------------------------------------------------------
// Entry point
// ---------------------------------------------------------------------------
extern "C" void kernel_launch(void* const* d_in, const int* in_sizes, int n_in,
                              void* d_out, int out_size)
{
    const float* Q = (const float*)d_in[0];   // decoder_hidden  [16,1024,1024]
    const float* E = (const float*)d_in[1];   // encoder_outputs [16,1024,1024]
    float* O = (float*)d_out;                 // context         [16,1024,1024]

    cudaFuncSetAttribute(gemm_kernel, cudaFuncAttributeMaxDynamicSharedMemorySize,
                         GEMM_SMEM);

    const int nblk = (int)(NELEM / 8 / 256);  // 8192
    split_kernel<<<nblk, 256>>>(Q, 0);
    split_kernel<<<nblk, 256>>>(E, 1);
    transpose_kernel<<<dim3(16, 16, 16), 256>>>();

    dim3 grd(NN / 128, NN / 128, NB);                             // (8,8,16)
    gemm_kernel<<<grd, 128, GEMM_SMEM>>>(nullptr, 0);             // S = Q·E^T
    softmax_kernel<<<NB * NN, 128>>>();                           // P + bf16 split
    gemm_kernel<<<grd, 128, GEMM_SMEM>>>(O, 1);                   // O = P·E
}

// round 11
// speedup vs baseline: 1.7975x; 1.7975x over previous
#include <cuda_runtime.h>
#include <cuda_bf16.h>
#include <cstdint>

#define NB 16
#define NN 1024
#define NELEM ((size_t)NB * NN * NN)

// ---------------------------------------------------------------------------
// Scratch (device globals — allocation-free)
// ---------------------------------------------------------------------------
__device__ float          g_scores[NELEM];                 // fp32 scores S
__device__ __nv_bfloat16  g_q0[NELEM], g_q1[NELEM];        // Q split
__device__ __nv_bfloat16  g_e0[NELEM], g_e1[NELEM];        // E split (row-major)
__device__ __nv_bfloat16  g_e0t[NELEM], g_e1t[NELEM];      // E split transposed
__device__ __nv_bfloat16  g_p0[NELEM], g_p1[NELEM];        // softmax probs split

// ---------------------------------------------------------------------------
// PTX helpers (sm_80-era ISA only: mma.sync / ldmatrix / cp.async)
// ---------------------------------------------------------------------------
__device__ __forceinline__ uint32_t smem_u32(const void* p) {
    return (uint32_t)__cvta_generic_to_shared(p);
}
__device__ __forceinline__ void cp16(uint32_t saddr, const void* g) {
    asm volatile("cp.async.cg.shared.global [%0], [%1], 16;" :: "r"(saddr), "l"(g));
}
#define CP_COMMIT()  asm volatile("cp.async.commit_group;" ::: "memory")
#define CP_WAIT1()   asm volatile("cp.async.wait_group 1;" ::: "memory")

#define LDSM4(r, addr) \
    asm volatile("ldmatrix.sync.aligned.m8n8.x4.shared.b16 {%0,%1,%2,%3}, [%4];" \
        : "=r"((r)[0]), "=r"((r)[1]), "=r"((r)[2]), "=r"((r)[3]) : "r"(addr))

#define MMA16816(d, a, b) \
    asm volatile("mma.sync.aligned.m16n8k16.row.col.f32.bf16.bf16.f32 " \
        "{%0,%1,%2,%3}, {%4,%5,%6,%7}, {%8,%9}, {%0,%1,%2,%3};" \
        : "+f"((d)[0]), "+f"((d)[1]), "+f"((d)[2]), "+f"((d)[3]) \
        : "r"((a)[0]), "r"((a)[1]), "r"((a)[2]), "r"((a)[3]), \
          "r"((b)[0]), "r"((b)[1]))

// ---------------------------------------------------------------------------
// fp32 -> 2-term bf16 split (which=0: Q->q0,q1 ; which=1: E->e0,e1)
// ---------------------------------------------------------------------------
__global__ __launch_bounds__(256) void split_kernel(const float* __restrict__ x, int which)
{
    size_t i = ((size_t)blockIdx.x * 256 + threadIdx.x) * 8;
    float4 a = *(const float4*)(x + i);
    float4 b = *(const float4*)(x + i + 4);
    float v[8] = {a.x, a.y, a.z, a.w, b.x, b.y, b.z, b.w};
    __nv_bfloat16 h0[8], h1[8];
#pragma unroll
    for (int j = 0; j < 8; j++) {
        h0[j] = __float2bfloat16(v[j]);
        h1[j] = __float2bfloat16(v[j] - __bfloat162float(h0[j]));
    }
    __nv_bfloat16* o0 = which ? g_e0 : g_q0;
    __nv_bfloat16* o1 = which ? g_e1 : g_q1;
    *(uint4*)(o0 + i) = *(const uint4*)h0;
    *(uint4*)(o1 + i) = *(const uint4*)h1;
}

// ---------------------------------------------------------------------------
// Transpose e0,e1 -> e0t,e1t  (per batch, 64x64 tiles)
// ---------------------------------------------------------------------------
__global__ __launch_bounds__(256) void transpose_kernel()
{
    __shared__ __nv_bfloat16 tile[64][72];
    const int bj = blockIdx.x, bi = blockIdx.y;
    const size_t boff = (size_t)blockIdx.z * NN * NN;
    const int t = threadIdx.x;

#pragma unroll
    for (int arr = 0; arr < 2; arr++) {
        const __nv_bfloat16* src = arr ? g_e1 : g_e0;
        __nv_bfloat16*       dst = arr ? g_e1t : g_e0t;
        if (arr) __syncthreads();
#pragma unroll
        for (int i = 0; i < 2; i++) {
            int v = t + i * 256;
            int r = v >> 3, j = v & 7;
            *(uint4*)&tile[r][j * 8] =
                *(const uint4*)(src + boff + (size_t)(bi * 64 + r) * NN + bj * 64 + j * 8);
        }
        __syncthreads();
#pragma unroll
        for (int i = 0; i < 2; i++) {
            int v = t + i * 256;
            int r = v >> 3, j = v & 7;
            __nv_bfloat16 out[8];
#pragma unroll
            for (int c = 0; c < 8; c++) out[c] = tile[j * 8 + c][r];
            *(uint4*)(dst + boff + (size_t)(bj * 64 + r) * NN + bi * 64 + j * 8) =
                *(const uint4*)out;
        }
    }
}

// ---------------------------------------------------------------------------
// HMMA GEMM (NT): C[128x128 tile] = A0·B0^T + A0·B1^T + A1·B0^T
//   mode 0: A=q0/q1, B=e0/e1, C=g_scores   (S = Q·E^T)
//   mode 1: A=p0/p1, B=e0t/e1t, C=Cout     (O = P·E)
// Operands K-major [rows x 1024] bf16. BK=32, 3-stage cp.async pipeline,
// 96 KB smem -> 2 CTAs/SM (16 warps).
// Swizzle: chunk c of row r stored at ((c ^ ((r>>1)&3)) << 4) within the 64B
// row — makes each ldmatrix 8-row phase hit distinct (half, chunk) bank sets
// (the previous c ^ (r&3) swizzle had rows r and r+4 colliding -> 2-way
// conflict on every LDSM).
// smem stage: A0 | A1 | B0 | B1, each 128x32 bf16 (64B rows).
// ---------------------------------------------------------------------------
#define STAGE_BYTES 32768
#define GEMM_SMEM   (3 * STAGE_BYTES)

__global__ __launch_bounds__(256, 2) void gemm_kernel(float* __restrict__ Cout, int mode)
{
    extern __shared__ __align__(1024) char smem[];
    const uint32_t sbase = smem_u32(smem);

    const int t = threadIdx.x;
    const int lane = t & 31, w = t >> 5;
    const int wm = w >> 2, wn = w & 3;          // 2 x 4 warp grid, 64x32 warp tile

    const size_t boff = (size_t)blockIdx.z * NN * NN;
    const int m0 = blockIdx.y * 128, n0 = blockIdx.x * 128;

    const __nv_bfloat16* gsrc[4];
    gsrc[0] = (mode ? g_p0  : g_q0) + boff + (size_t)m0 * NN;   // A comp0
    gsrc[1] = (mode ? g_p1  : g_q1) + boff + (size_t)m0 * NN;   // A comp1
    gsrc[2] = (mode ? g_e0t : g_e0) + boff + (size_t)n0 * NN;   // B comp0
    gsrc[3] = (mode ? g_e1t : g_e1) + boff + (size_t)n0 * NN;   // B comp1
    float* Cb = (mode ? Cout : g_scores) + boff;

    // --- gmem->smem mapping: per tile, 512 x 16B chunks; 2 per thread -------
    const int r0 = t >> 2, c0 = t & 3;                  // rows r0, r0+64
    const uint32_t so0 = (uint32_t)(r0 * 64 + ((c0 ^ ((r0 >> 1) & 3)) << 4));
    const uint32_t so1 = so0 + 64 * 64;   // ((r0+64)>>1)&3 == (r0>>1)&3

    float acc[4][4][4];
#pragma unroll
    for (int i = 0; i < 4; i++)
#pragma unroll
        for (int j = 0; j < 4; j++)
#pragma unroll
            for (int r = 0; r < 4; r++) acc[i][j][r] = 0.f;

    // --- pipeline prologue: stages 0,1 --------------------------------------
#pragma unroll
    for (int s = 0; s < 2; s++) {
        const uint32_t sb = sbase + s * STAGE_BYTES;
        const size_t go = (size_t)s * 32 + (size_t)c0 * 8;
#pragma unroll
        for (int a = 0; a < 4; a++) {
            cp16(sb + a * 8192 + so0, gsrc[a] + (size_t)r0 * NN + go);
            cp16(sb + a * 8192 + so1, gsrc[a] + (size_t)(r0 + 64) * NN + go);
        }
        CP_COMMIT();
    }

    // --- ldmatrix per-lane offsets ------------------------------------------
    const uint32_t rowA = (uint32_t)(wm * 64 + (lane & 15));
    const uint32_t hiA  = (uint32_t)(lane >> 4);
    const uint32_t rowB = (uint32_t)(wn * 32 + ((lane >> 4) << 3) + (lane & 7));
    const uint32_t hiB  = (uint32_t)((lane >> 3) & 1);
    // swizzle term: (row>>1)&3 reduces to (lane>>1)&3 for both A and B rows,
    // and is invariant under the +16/+32/+48 row offsets used below.
    const uint32_t lr   = (uint32_t)((lane >> 1) & 3);

    // --- mainloop: 32 iterations of BK=32 -----------------------------------
    int buf = 0;                                  // kt % 3
    int nbuf = 2;                                 // (kt+2) % 3
#pragma unroll 1
    for (int kt = 0; kt < 32; kt++) {
        CP_WAIT1();
        __syncthreads();

        // issue loads for stage kt+2 (buffer consumed at iter kt-1)
        if (kt < 30) {
            const uint32_t sb = sbase + nbuf * STAGE_BYTES;
            const size_t go = (size_t)(kt + 2) * 32 + (size_t)c0 * 8;
#pragma unroll
            for (int a = 0; a < 4; a++) {
                cp16(sb + a * 8192 + so0, gsrc[a] + (size_t)r0 * NN + go);
                cp16(sb + a * 8192 + so1, gsrc[a] + (size_t)(r0 + 64) * NN + go);
            }
        }
        CP_COMMIT();

        const uint32_t base = sbase + buf * STAGE_BYTES;
#pragma unroll
        for (int ks = 0; ks < 2; ks++) {
            const uint32_t kb = (uint32_t)(ks * 2);
            uint32_t bf0[8], bf1[8], af[16];

            const uint32_t offB = rowB * 64 + (((kb + hiB) ^ lr) << 4);
            LDSM4(bf0,     base + 16384 + offB);
            LDSM4(bf0 + 4, base + 16384 + offB + 16 * 64);
            LDSM4(bf1,     base + 24576 + offB);
            LDSM4(bf1 + 4, base + 24576 + offB + 16 * 64);

            const uint32_t offA = rowA * 64 + (((kb + hiA) ^ lr) << 4);
            LDSM4(af,      base + offA);
            LDSM4(af + 4,  base + offA + 16 * 64);
            LDSM4(af + 8,  base + offA + 32 * 64);
            LDSM4(af + 12, base + offA + 48 * 64);

#pragma unroll
            for (int mt = 0; mt < 4; mt++)
#pragma unroll
                for (int nt = 0; nt < 4; nt++)
                    MMA16816(acc[mt][nt], af + mt * 4, bf0 + nt * 2);
#pragma unroll
            for (int mt = 0; mt < 4; mt++)
#pragma unroll
                for (int nt = 0; nt < 4; nt++)
                    MMA16816(acc[mt][nt], af + mt * 4, bf1 + nt * 2);

            // A comp1 (q1 / p1) reuses af registers
            LDSM4(af,      base + 8192 + offA);
            LDSM4(af + 4,  base + 8192 + offA + 16 * 64);
            LDSM4(af + 8,  base + 8192 + offA + 32 * 64);
            LDSM4(af + 12, base + 8192 + offA + 48 * 64);
#pragma unroll
            for (int mt = 0; mt < 4; mt++)
#pragma unroll
                for (int nt = 0; nt < 4; nt++)
                    MMA16816(acc[mt][nt], af + mt * 4, bf0 + nt * 2);
        }

        buf  = (buf  == 2) ? 0 : buf + 1;
        nbuf = (nbuf == 2) ? 0 : nbuf + 1;
    }

    // --- epilogue: direct fp32 stores ---------------------------------------
    const int er = lane >> 2, ec = (lane & 3) * 2;
#pragma unroll
    for (int mt = 0; mt < 4; mt++) {
        const int rr = m0 + wm * 64 + mt * 16 + er;
#pragma unroll
        for (int nt = 0; nt < 4; nt++) {
            const int cc = n0 + wn * 32 + nt * 8 + ec;
            *(float2*)&Cb[(size_t)rr * NN + cc] =
                make_float2(acc[mt][nt][0], acc[mt][nt][1]);
            *(float2*)&Cb[(size_t)(rr + 8) * NN + cc] =
                make_float2(acc[mt][nt][2], acc[mt][nt][3]);
        }
    }
}

// ---------------------------------------------------------------------------
// Row softmax over g_scores; writes 2-term bf16 split of probs to g_p0,g_p1
// ---------------------------------------------------------------------------
__global__ __launch_bounds__(128) void softmax_kernel()
{
    __shared__ float red[4];
    const size_t rowoff = (size_t)blockIdx.x * NN;
    const float* p = g_scores + rowoff;
    const int t = threadIdx.x, lane = t & 31, wid = t >> 5;

    float4 v0 = ((const float4*)p)[t];
    float4 v1 = ((const float4*)p)[t + 128];

    float m = fmaxf(fmaxf(fmaxf(v0.x, v0.y), fmaxf(v0.z, v0.w)),
                    fmaxf(fmaxf(v1.x, v1.y), fmaxf(v1.z, v1.w)));
#pragma unroll
    for (int off = 16; off > 0; off >>= 1)
        m = fmaxf(m, __shfl_xor_sync(0xffffffffu, m, off));
    if (lane == 0) red[wid] = m;
    __syncthreads();
    m = fmaxf(fmaxf(red[0], red[1]), fmaxf(red[2], red[3]));
    __syncthreads();

    v0.x = __expf(v0.x - m); v0.y = __expf(v0.y - m);
    v0.z = __expf(v0.z - m); v0.w = __expf(v0.w - m);
    v1.x = __expf(v1.x - m); v1.y = __expf(v1.y - m);
    v1.z = __expf(v1.z - m); v1.w = __expf(v1.w - m);

    float s = v0.x + v0.y + v0.z + v0.w + v1.x + v1.y + v1.z + v1.w;
#pragma unroll
    for (int off = 16; off > 0; off >>= 1)
        s += __shfl_xor_sync(0xffffffffu, s, off);
    if (lane == 0) red[wid] = s;
    __syncthreads();
    s = red[0] + red[1] + red[2] + red[3];
    const float inv = 1.0f / s;

    float w0[4] = {v0.x * inv, v0.y * inv, v0.z * inv, v0.w * inv};
    float w1[4] = {v1.x * inv, v1.y * inv, v1.z * inv, v1.w * inv};

    __nv_bfloat16 a0[4], a1[4], b0[4], b1[4];
#pragma unroll
    for (int j = 0; j < 4; j++) {
        a0[j] = __float2bfloat16(w0[j]);
        a1[j] = __float2bfloat16(w0[j] - __bfloat162float(a0[j]));
        b0[j] = __float2bfloat16(w1[j]);
        b1[j] = __float2bfloat16(w1[j] - __bfloat162float(b0[j]));
    }
    *(uint2*)(g_p0 + rowoff + t * 4)       = *(const uint2*)a0;
    *(uint2*)(g_p1 + rowoff + t * 4)       = *(const uint2*)a1;
    *(uint2*)(g_p0 + rowoff + 512 + t * 4) = *(const uint2*)b0;
    *(uint2*)(g_p1 + rowoff + 512 + t * 4) = *(const uint2*)b1;
}

// ---------------------------------------------------------------------------
// Entry point
// ---------------------------------------------------------------------------
extern "C" void kernel_launch(void* const* d_in, const int* in_sizes, int n_in,
                              void* d_out, int out_size)
{
    const float* Q = (const float*)d_in[0];   // decoder_hidden  [16,1024,1024]
    const float* E = (const float*)d_in[1];   // encoder_outputs [16,1024,1024]
    float* O = (float*)d_out;                 // context         [16,1024,1024]

    cudaFuncSetAttribute(gemm_kernel, cudaFuncAttributeMaxDynamicSharedMemorySize,
                         GEMM_SMEM);

    const int nblk = (int)(NELEM / 8 / 256);  // 8192
    split_kernel<<<nblk, 256>>>(Q, 0);
    split_kernel<<<nblk, 256>>>(E, 1);
    transpose_kernel<<<dim3(16, 16, 16), 256>>>();

    dim3 grd(NN / 128, NN / 128, NB);                             // (8,8,16)
    gemm_kernel<<<grd, 256, GEMM_SMEM>>>(nullptr, 0);             // S = Q·E^T
    softmax_kernel<<<NB * NN, 128>>>();                           // P + bf16 split
    gemm_kernel<<<grd, 256, GEMM_SMEM>>>(O, 1);                   // O = P·E
}

// round 12
// speedup vs baseline: 1.8360x; 1.0214x over previous
#include <cuda_runtime.h>
#include <cuda_bf16.h>
#include <cstdint>

#define NB 16
#define NN 1024
#define NELEM ((size_t)NB * NN * NN)

// ---------------------------------------------------------------------------
// Scratch (device globals — allocation-free)
// ---------------------------------------------------------------------------
__device__ float          g_scores[NELEM];                 // fp32 scores S
__device__ __nv_bfloat16  g_q0[NELEM], g_q1[NELEM];        // Q split
__device__ __nv_bfloat16  g_e0[NELEM], g_e1[NELEM];        // E split (row-major)
__device__ __nv_bfloat16  g_e0t[NELEM], g_e1t[NELEM];      // E split transposed
__device__ __nv_bfloat16  g_p0[NELEM], g_p1[NELEM];        // softmax probs split

// ---------------------------------------------------------------------------
// PTX helpers (sm_80-era ISA only: mma.sync / ldmatrix / cp.async)
// ---------------------------------------------------------------------------
__device__ __forceinline__ uint32_t smem_u32(const void* p) {
    return (uint32_t)__cvta_generic_to_shared(p);
}
__device__ __forceinline__ void cp16(uint32_t saddr, const void* g) {
    asm volatile("cp.async.cg.shared.global [%0], [%1], 16;" :: "r"(saddr), "l"(g));
}
#define CP_COMMIT()  asm volatile("cp.async.commit_group;" ::: "memory")
#define CP_WAIT1()   asm volatile("cp.async.wait_group 1;" ::: "memory")

#define LDSM4(r, addr) \
    asm volatile("ldmatrix.sync.aligned.m8n8.x4.shared.b16 {%0,%1,%2,%3}, [%4];" \
        : "=r"((r)[0]), "=r"((r)[1]), "=r"((r)[2]), "=r"((r)[3]) : "r"(addr))

#define MMA16816(d, a, b) \
    asm volatile("mma.sync.aligned.m16n8k16.row.col.f32.bf16.bf16.f32 " \
        "{%0,%1,%2,%3}, {%4,%5,%6,%7}, {%8,%9}, {%0,%1,%2,%3};" \
        : "+f"((d)[0]), "+f"((d)[1]), "+f"((d)[2]), "+f"((d)[3]) \
        : "r"((a)[0]), "r"((a)[1]), "r"((a)[2]), "r"((a)[3]), \
          "r"((b)[0]), "r"((b)[1]))

// ---------------------------------------------------------------------------
// Q: fp32 -> 2-term bf16 split (flat)
// ---------------------------------------------------------------------------
__global__ __launch_bounds__(256) void split_q_kernel(const float* __restrict__ x)
{
    size_t i = ((size_t)blockIdx.x * 256 + threadIdx.x) * 8;
    float4 a = *(const float4*)(x + i);
    float4 b = *(const float4*)(x + i + 4);
    float v[8] = {a.x, a.y, a.z, a.w, b.x, b.y, b.z, b.w};
    __nv_bfloat16 h0[8], h1[8];
#pragma unroll
    for (int j = 0; j < 8; j++) {
        h0[j] = __float2bfloat16(v[j]);
        h1[j] = __float2bfloat16(v[j] - __bfloat162float(h0[j]));
    }
    *(uint4*)(g_q0 + i) = *(const uint4*)h0;
    *(uint4*)(g_q1 + i) = *(const uint4*)h1;
}

// ---------------------------------------------------------------------------
// E: fp32 -> 2-term bf16 split, writing BOTH row-major (e0,e1) and
// transposed (e0t,e1t) in one pass (64x64 tiles, smem staging).
// Replaces the former split(E) + transpose kernels (saves 128 MB traffic).
// ---------------------------------------------------------------------------
__global__ __launch_bounds__(256) void split_e_kernel(const float* __restrict__ x)
{
    __shared__ __nv_bfloat16 t0[64][72];
    __shared__ __nv_bfloat16 t1[64][72];
    const int bj = blockIdx.x, bi = blockIdx.y;       // col tile, row tile
    const size_t boff = (size_t)blockIdx.z * NN * NN;
    const int t = threadIdx.x;
    const int r = t >> 3, c = (t & 7) * 8;            // r: 0..31, c: 0..56

#pragma unroll
    for (int h = 0; h < 2; h++) {
        const int rr = r + h * 32;                    // 0..63 within tile
        const int grow = bi * 64 + rr;
        const float* src = x + boff + (size_t)grow * NN + bj * 64 + c;
        float4 a = *(const float4*)src;
        float4 b = *(const float4*)(src + 4);
        float v[8] = {a.x, a.y, a.z, a.w, b.x, b.y, b.z, b.w};
        __nv_bfloat16 h0[8], h1[8];
#pragma unroll
        for (int j = 0; j < 8; j++) {
            h0[j] = __float2bfloat16(v[j]);
            h1[j] = __float2bfloat16(v[j] - __bfloat162float(h0[j]));
        }
        // row-major outputs (coalesced)
        *(uint4*)(g_e0 + boff + (size_t)grow * NN + bj * 64 + c) = *(const uint4*)h0;
        *(uint4*)(g_e1 + boff + (size_t)grow * NN + bj * 64 + c) = *(const uint4*)h1;
        // stage for transpose
        *(uint4*)&t0[rr][c] = *(const uint4*)h0;
        *(uint4*)&t1[rr][c] = *(const uint4*)h1;
    }
    __syncthreads();

    // transposed outputs: out(j, i) = tile(i, j)
#pragma unroll
    for (int h = 0; h < 2; h++) {
        const int j = r + h * 32;                     // transposed row (orig col)
        __nv_bfloat16 o0[8], o1[8];
#pragma unroll
        for (int cc = 0; cc < 8; cc++) {
            o0[cc] = t0[c + cc][j];
            o1[cc] = t1[c + cc][j];
        }
        __nv_bfloat16* d0 = g_e0t + boff + (size_t)(bj * 64 + j) * NN + bi * 64 + c;
        __nv_bfloat16* d1 = g_e1t + boff + (size_t)(bj * 64 + j) * NN + bi * 64 + c;
        *(uint4*)d0 = *(const uint4*)o0;
        *(uint4*)d1 = *(const uint4*)o1;
    }
}

// ---------------------------------------------------------------------------
// HMMA GEMM (NT): C[128x128 tile] = A0·B0^T + A0·B1^T + A1·B0^T
//   mode 0: A=q0/q1, B=e0/e1, C=g_scores   (S = Q·E^T)
//   mode 1: A=p0/p1, B=e0t/e1t, C=Cout     (O = P·E)
// Operands K-major [rows x 1024] bf16. BK=32, 3-stage cp.async pipeline,
// 96 KB smem -> 2 CTAs/SM (16 warps).
// Swizzle: chunk c of row r at ((c ^ ((r>>1)&3)) << 4) — conflict-free for
// both the 4-phase STS and every ldmatrix 8-row phase.
// smem stage: A0 | A1 | B0 | B1, each 128x32 bf16 (64B rows).
// (identical to round-11 kernel)
// ---------------------------------------------------------------------------
#define STAGE_BYTES 32768
#define GEMM_SMEM   (3 * STAGE_BYTES)

__global__ __launch_bounds__(256, 2) void gemm_kernel(float* __restrict__ Cout, int mode)
{
    extern __shared__ __align__(1024) char smem[];
    const uint32_t sbase = smem_u32(smem);

    const int t = threadIdx.x;
    const int lane = t & 31, w = t >> 5;
    const int wm = w >> 2, wn = w & 3;          // 2 x 4 warp grid, 64x32 warp tile

    const size_t boff = (size_t)blockIdx.z * NN * NN;
    const int m0 = blockIdx.y * 128, n0 = blockIdx.x * 128;

    const __nv_bfloat16* gsrc[4];
    gsrc[0] = (mode ? g_p0  : g_q0) + boff + (size_t)m0 * NN;   // A comp0
    gsrc[1] = (mode ? g_p1  : g_q1) + boff + (size_t)m0 * NN;   // A comp1
    gsrc[2] = (mode ? g_e0t : g_e0) + boff + (size_t)n0 * NN;   // B comp0
    gsrc[3] = (mode ? g_e1t : g_e1) + boff + (size_t)n0 * NN;   // B comp1
    float* Cb = (mode ? Cout : g_scores) + boff;

    // --- gmem->smem mapping: per tile, 512 x 16B chunks; 2 per thread -------
    const int r0 = t >> 2, c0 = t & 3;                  // rows r0, r0+64
    const uint32_t so0 = (uint32_t)(r0 * 64 + ((c0 ^ ((r0 >> 1) & 3)) << 4));
    const uint32_t so1 = so0 + 64 * 64;   // ((r0+64)>>1)&3 == (r0>>1)&3

    float acc[4][4][4];
#pragma unroll
    for (int i = 0; i < 4; i++)
#pragma unroll
        for (int j = 0; j < 4; j++)
#pragma unroll
            for (int r = 0; r < 4; r++) acc[i][j][r] = 0.f;

    // --- pipeline prologue: stages 0,1 --------------------------------------
#pragma unroll
    for (int s = 0; s < 2; s++) {
        const uint32_t sb = sbase + s * STAGE_BYTES;
        const size_t go = (size_t)s * 32 + (size_t)c0 * 8;
#pragma unroll
        for (int a = 0; a < 4; a++) {
            cp16(sb + a * 8192 + so0, gsrc[a] + (size_t)r0 * NN + go);
            cp16(sb + a * 8192 + so1, gsrc[a] + (size_t)(r0 + 64) * NN + go);
        }
        CP_COMMIT();
    }

    // --- ldmatrix per-lane offsets ------------------------------------------
    const uint32_t rowA = (uint32_t)(wm * 64 + (lane & 15));
    const uint32_t hiA  = (uint32_t)(lane >> 4);
    const uint32_t rowB = (uint32_t)(wn * 32 + ((lane >> 4) << 3) + (lane & 7));
    const uint32_t hiB  = (uint32_t)((lane >> 3) & 1);
    const uint32_t lr   = (uint32_t)((lane >> 1) & 3);

    // --- mainloop: 32 iterations of BK=32 -----------------------------------
    int buf = 0;                                  // kt % 3
    int nbuf = 2;                                 // (kt+2) % 3
#pragma unroll 1
    for (int kt = 0; kt < 32; kt++) {
        CP_WAIT1();
        __syncthreads();

        // issue loads for stage kt+2 (buffer consumed at iter kt-1)
        if (kt < 30) {
            const uint32_t sb = sbase + nbuf * STAGE_BYTES;
            const size_t go = (size_t)(kt + 2) * 32 + (size_t)c0 * 8;
#pragma unroll
            for (int a = 0; a < 4; a++) {
                cp16(sb + a * 8192 + so0, gsrc[a] + (size_t)r0 * NN + go);
                cp16(sb + a * 8192 + so1, gsrc[a] + (size_t)(r0 + 64) * NN + go);
            }
        }
        CP_COMMIT();

        const uint32_t base = sbase + buf * STAGE_BYTES;
#pragma unroll
        for (int ks = 0; ks < 2; ks++) {
            const uint32_t kb = (uint32_t)(ks * 2);
            uint32_t bf0[8], bf1[8], af[16];

            const uint32_t offB = rowB * 64 + (((kb + hiB) ^ lr) << 4);
            LDSM4(bf0,     base + 16384 + offB);
            LDSM4(bf0 + 4, base + 16384 + offB + 16 * 64);
            LDSM4(bf1,     base + 24576 + offB);
            LDSM4(bf1 + 4, base + 24576 + offB + 16 * 64);

            const uint32_t offA = rowA * 64 + (((kb + hiA) ^ lr) << 4);
            LDSM4(af,      base + offA);
            LDSM4(af + 4,  base + offA + 16 * 64);
            LDSM4(af + 8,  base + offA + 32 * 64);
            LDSM4(af + 12, base + offA + 48 * 64);

#pragma unroll
            for (int mt = 0; mt < 4; mt++)
#pragma unroll
                for (int nt = 0; nt < 4; nt++)
                    MMA16816(acc[mt][nt], af + mt * 4, bf0 + nt * 2);
#pragma unroll
            for (int mt = 0; mt < 4; mt++)
#pragma unroll
                for (int nt = 0; nt < 4; nt++)
                    MMA16816(acc[mt][nt], af + mt * 4, bf1 + nt * 2);

            // A comp1 (q1 / p1) reuses af registers
            LDSM4(af,      base + 8192 + offA);
            LDSM4(af + 4,  base + 8192 + offA + 16 * 64);
            LDSM4(af + 8,  base + 8192 + offA + 32 * 64);
            LDSM4(af + 12, base + 8192 + offA + 48 * 64);
#pragma unroll
            for (int mt = 0; mt < 4; mt++)
#pragma unroll
                for (int nt = 0; nt < 4; nt++)
                    MMA16816(acc[mt][nt], af + mt * 4, bf0 + nt * 2);
        }

        buf  = (buf  == 2) ? 0 : buf + 1;
        nbuf = (nbuf == 2) ? 0 : nbuf + 1;
    }

    // --- epilogue: direct fp32 stores ---------------------------------------
    const int er = lane >> 2, ec = (lane & 3) * 2;
#pragma unroll
    for (int mt = 0; mt < 4; mt++) {
        const int rr = m0 + wm * 64 + mt * 16 + er;
#pragma unroll
        for (int nt = 0; nt < 4; nt++) {
            const int cc = n0 + wn * 32 + nt * 8 + ec;
            *(float2*)&Cb[(size_t)rr * NN + cc] =
                make_float2(acc[mt][nt][0], acc[mt][nt][1]);
            *(float2*)&Cb[(size_t)(rr + 8) * NN + cc] =
                make_float2(acc[mt][nt][2], acc[mt][nt][3]);
        }
    }
}

// ---------------------------------------------------------------------------
// Row softmax over g_scores; writes 2-term bf16 split of probs to g_p0,g_p1
// ---------------------------------------------------------------------------
__global__ __launch_bounds__(128) void softmax_kernel()
{
    __shared__ float red[4];
    const size_t rowoff = (size_t)blockIdx.x * NN;
    const float* p = g_scores + rowoff;
    const int t = threadIdx.x, lane = t & 31, wid = t >> 5;

    float4 v0 = ((const float4*)p)[t];
    float4 v1 = ((const float4*)p)[t + 128];

    float m = fmaxf(fmaxf(fmaxf(v0.x, v0.y), fmaxf(v0.z, v0.w)),
                    fmaxf(fmaxf(v1.x, v1.y), fmaxf(v1.z, v1.w)));
#pragma unroll
    for (int off = 16; off > 0; off >>= 1)
        m = fmaxf(m, __shfl_xor_sync(0xffffffffu, m, off));
    if (lane == 0) red[wid] = m;
    __syncthreads();
    m = fmaxf(fmaxf(red[0], red[1]), fmaxf(red[2], red[3]));
    __syncthreads();

    v0.x = __expf(v0.x - m); v0.y = __expf(v0.y - m);
    v0.z = __expf(v0.z - m); v0.w = __expf(v0.w - m);
    v1.x = __expf(v1.x - m); v1.y = __expf(v1.y - m);
    v1.z = __expf(v1.z - m); v1.w = __expf(v1.w - m);

    float s = v0.x + v0.y + v0.z + v0.w + v1.x + v1.y + v1.z + v1.w;
#pragma unroll
    for (int off = 16; off > 0; off >>= 1)
        s += __shfl_xor_sync(0xffffffffu, s, off);
    if (lane == 0) red[wid] = s;
    __syncthreads();
    s = red[0] + red[1] + red[2] + red[3];
    const float inv = 1.0f / s;

    float w0[4] = {v0.x * inv, v0.y * inv, v0.z * inv, v0.w * inv};
    float w1[4] = {v1.x * inv, v1.y * inv, v1.z * inv, v1.w * inv};

    __nv_bfloat16 a0[4], a1[4], b0[4], b1[4];
#pragma unroll
    for (int j = 0; j < 4; j++) {
        a0[j] = __float2bfloat16(w0[j]);
        a1[j] = __float2bfloat16(w0[j] - __bfloat162float(a0[j]));
        b0[j] = __float2bfloat16(w1[j]);
        b1[j] = __float2bfloat16(w1[j] - __bfloat162float(b0[j]));
    }
    *(uint2*)(g_p0 + rowoff + t * 4)       = *(const uint2*)a0;
    *(uint2*)(g_p1 + rowoff + t * 4)       = *(const uint2*)a1;
    *(uint2*)(g_p0 + rowoff + 512 + t * 4) = *(const uint2*)b0;
    *(uint2*)(g_p1 + rowoff + 512 + t * 4) = *(const uint2*)b1;
}

// ---------------------------------------------------------------------------
// Entry point
// ---------------------------------------------------------------------------
extern "C" void kernel_launch(void* const* d_in, const int* in_sizes, int n_in,
                              void* d_out, int out_size)
{
    const float* Q = (const float*)d_in[0];   // decoder_hidden  [16,1024,1024]
    const float* E = (const float*)d_in[1];   // encoder_outputs [16,1024,1024]
    float* O = (float*)d_out;                 // context         [16,1024,1024]

    cudaFuncSetAttribute(gemm_kernel, cudaFuncAttributeMaxDynamicSharedMemorySize,
                         GEMM_SMEM);

    split_q_kernel<<<(int)(NELEM / 8 / 256), 256>>>(Q);
    split_e_kernel<<<dim3(16, 16, 16), 256>>>(E);     // split + transpose fused

    dim3 grd(NN / 128, NN / 128, NB);                             // (8,8,16)
    gemm_kernel<<<grd, 256, GEMM_SMEM>>>(nullptr, 0);             // S = Q·E^T
    softmax_kernel<<<NB * NN, 128>>>();                           // P + bf16 split
    gemm_kernel<<<grd, 256, GEMM_SMEM>>>(O, 1);                   // O = P·E
}

// round 15
// speedup vs baseline: 1.9688x; 1.0723x over previous
#include <cuda_runtime.h>
#include <cuda_bf16.h>
#include <cstdint>

#define NB 16
#define NN 1024
#define NELEM ((size_t)NB * NN * NN)

// ---------------------------------------------------------------------------
// Scratch (device globals — allocation-free)
// ---------------------------------------------------------------------------
__device__ float          g_scores[NELEM];                 // fp32 scores S
__device__ __nv_bfloat16  g_q0[NELEM], g_q1[NELEM];        // Q split
__device__ __nv_bfloat16  g_e0[NELEM], g_e1[NELEM];        // E split (row-major)
__device__ __nv_bfloat16  g_e0t[NELEM], g_e1t[NELEM];      // E split transposed
__device__ __nv_bfloat16  g_p0[NELEM], g_p1[NELEM];        // softmax probs split

// ---------------------------------------------------------------------------
// PTX helpers (sm_80-era ISA only: mma.sync / ldmatrix / cp.async)
// ---------------------------------------------------------------------------
__device__ __forceinline__ uint32_t smem_u32(const void* p) {
    return (uint32_t)__cvta_generic_to_shared(p);
}
__device__ __forceinline__ void cp16(uint32_t saddr, const void* g) {
    asm volatile("cp.async.cg.shared.global [%0], [%1], 16;" :: "r"(saddr), "l"(g));
}
#define CP_COMMIT()  asm volatile("cp.async.commit_group;" ::: "memory")
#define CP_WAIT1()   asm volatile("cp.async.wait_group 1;" ::: "memory")

#define LDSM4(r, addr) \
    asm volatile("ldmatrix.sync.aligned.m8n8.x4.shared.b16 {%0,%1,%2,%3}, [%4];" \
        : "=r"((r)[0]), "=r"((r)[1]), "=r"((r)[2]), "=r"((r)[3]) : "r"(addr))

#define MMA16816(d, a, b) \
    asm volatile("mma.sync.aligned.m16n8k16.row.col.f32.bf16.bf16.f32 " \
        "{%0,%1,%2,%3}, {%4,%5,%6,%7}, {%8,%9}, {%0,%1,%2,%3};" \
        : "+f"((d)[0]), "+f"((d)[1]), "+f"((d)[2]), "+f"((d)[3]) \
        : "r"((a)[0]), "r"((a)[1]), "r"((a)[2]), "r"((a)[3]), \
          "r"((b)[0]), "r"((b)[1]))

// ---------------------------------------------------------------------------
// Fused input prep. Grid (16, 16, 32):
//   z < 16 : E batch z   — split + write row-major AND transposed (smem tile)
//   z >= 16: Q batch z-16 — flat split of one 64x64 tile
// ---------------------------------------------------------------------------
__global__ __launch_bounds__(256) void split_kernel(
    const float* __restrict__ Q, const float* __restrict__ E)
{
    __shared__ __nv_bfloat16 t0[64][72];
    __shared__ __nv_bfloat16 t1[64][72];
    const int bj = blockIdx.x, bi = blockIdx.y;
    const int t = threadIdx.x;
    const int r = t >> 3, c = (t & 7) * 8;            // r: 0..31, c: 0..56

    if (blockIdx.z >= 16) {                           // ---- Q path ----
        const size_t boff = (size_t)(blockIdx.z - 16) * NN * NN;
#pragma unroll
        for (int h = 0; h < 2; h++) {
            const int grow = bi * 64 + r + h * 32;
            const size_t off = boff + (size_t)grow * NN + bj * 64 + c;
            float4 a = *(const float4*)(Q + off);
            float4 b = *(const float4*)(Q + off + 4);
            float v[8] = {a.x, a.y, a.z, a.w, b.x, b.y, b.z, b.w};
            __nv_bfloat16 h0[8], h1[8];
#pragma unroll
            for (int j = 0; j < 8; j++) {
                h0[j] = __float2bfloat16(v[j]);
                h1[j] = __float2bfloat16(v[j] - __bfloat162float(h0[j]));
            }
            *(uint4*)(g_q0 + off) = *(const uint4*)h0;
            *(uint4*)(g_q1 + off) = *(const uint4*)h1;
        }
        return;
    }

    // ---- E path: split + transpose ----
    const size_t boff = (size_t)blockIdx.z * NN * NN;
#pragma unroll
    for (int h = 0; h < 2; h++) {
        const int rr = r + h * 32;
        const int grow = bi * 64 + rr;
        const size_t off = boff + (size_t)grow * NN + bj * 64 + c;
        float4 a = *(const float4*)(E + off);
        float4 b = *(const float4*)(E + off + 4);
        float v[8] = {a.x, a.y, a.z, a.w, b.x, b.y, b.z, b.w};
        __nv_bfloat16 h0[8], h1[8];
#pragma unroll
        for (int j = 0; j < 8; j++) {
            h0[j] = __float2bfloat16(v[j]);
            h1[j] = __float2bfloat16(v[j] - __bfloat162float(h0[j]));
        }
        *(uint4*)(g_e0 + off) = *(const uint4*)h0;
        *(uint4*)(g_e1 + off) = *(const uint4*)h1;
        *(uint4*)&t0[rr][c] = *(const uint4*)h0;
        *(uint4*)&t1[rr][c] = *(const uint4*)h1;
    }
    __syncthreads();

#pragma unroll
    for (int h = 0; h < 2; h++) {
        const int j = r + h * 32;                     // transposed row (orig col)
        __nv_bfloat16 o0[8], o1[8];
#pragma unroll
        for (int cc = 0; cc < 8; cc++) {
            o0[cc] = t0[c + cc][j];
            o1[cc] = t1[c + cc][j];
        }
        const size_t doff = boff + (size_t)(bj * 64 + j) * NN + bi * 64 + c;
        *(uint4*)(g_e0t + doff) = *(const uint4*)o0;
        *(uint4*)(g_e1t + doff) = *(const uint4*)o1;
    }
}

// ---------------------------------------------------------------------------
// HMMA GEMM (NT): C[128x128 tile] = A0·B0^T + A0·B1^T + A1·B0^T
//   mode 0: A=q0/q1, B=e0/e1, C=g_scores   (S = Q·E^T)
//   mode 1: A=p0/p1, B=e0t/e1t, C=Cout     (O = P·E)
// Operands K-major [rows x 1024] bf16. BK=32, 3-stage cp.async pipeline,
// 96 KB smem -> 2 CTAs/SM (16 warps).
// Loop order (PROVEN SAFE, round 11/12): CP_WAIT -> __syncthreads -> issue.
// The wait-then-barrier pair is load-bearing: wait covers only the warp's
// OWN cp.asyncs; the barrier makes every warp's completed copies visible
// before any LDSM. (Round 13's issue-before-wait broke exactly this.)
// cp.async issue placed between the ks=0 and ks=1 MMA chunks to spread LSU
// work away from the iteration-start LDSM burst (ordering-neutral: still
// after the barrier, one commit per iteration).
// Swizzle: chunk c of row r at ((c ^ ((r>>1)&3)) << 4) — conflict-free STS
// and conflict-free ldmatrix (validated round 11).
// ---------------------------------------------------------------------------
#define STAGE_BYTES 32768
#define GEMM_SMEM   (3 * STAGE_BYTES)

__global__ __launch_bounds__(256, 2) void gemm_kernel(float* __restrict__ Cout, int mode)
{
    extern __shared__ __align__(1024) char smem[];
    const uint32_t sbase = smem_u32(smem);

    const int t = threadIdx.x;
    const int lane = t & 31, w = t >> 5;
    const int wm = w >> 2, wn = w & 3;          // 2 x 4 warp grid, 64x32 warp tile

    const size_t boff = (size_t)blockIdx.z * NN * NN;
    const int m0 = blockIdx.y * 128, n0 = blockIdx.x * 128;

    const __nv_bfloat16* gsrc[4];
    gsrc[0] = (mode ? g_p0  : g_q0) + boff + (size_t)m0 * NN;   // A comp0
    gsrc[1] = (mode ? g_p1  : g_q1) + boff + (size_t)m0 * NN;   // A comp1
    gsrc[2] = (mode ? g_e0t : g_e0) + boff + (size_t)n0 * NN;   // B comp0
    gsrc[3] = (mode ? g_e1t : g_e1) + boff + (size_t)n0 * NN;   // B comp1
    float* Cb = (mode ? Cout : g_scores) + boff;

    // --- gmem->smem mapping: per tile, 512 x 16B chunks; 2 per thread -------
    const int r0 = t >> 2, c0 = t & 3;                  // rows r0, r0+64
    const uint32_t so0 = (uint32_t)(r0 * 64 + ((c0 ^ ((r0 >> 1) & 3)) << 4));
    const uint32_t so1 = so0 + 64 * 64;   // ((r0+64)>>1)&3 == (r0>>1)&3

    float acc[4][4][4];
#pragma unroll
    for (int i = 0; i < 4; i++)
#pragma unroll
        for (int j = 0; j < 4; j++)
#pragma unroll
            for (int r = 0; r < 4; r++) acc[i][j][r] = 0.f;

    // --- pipeline prologue: stages 0,1 --------------------------------------
#pragma unroll
    for (int s = 0; s < 2; s++) {
        const uint32_t sb = sbase + s * STAGE_BYTES;
        const size_t go = (size_t)s * 32 + (size_t)c0 * 8;
#pragma unroll
        for (int a = 0; a < 4; a++) {
            cp16(sb + a * 8192 + so0, gsrc[a] + (size_t)r0 * NN + go);
            cp16(sb + a * 8192 + so1, gsrc[a] + (size_t)(r0 + 64) * NN + go);
        }
        CP_COMMIT();
    }

    // --- ldmatrix per-lane offsets ------------------------------------------
    const uint32_t rowA = (uint32_t)(wm * 64 + (lane & 15));
    const uint32_t hiA  = (uint32_t)(lane >> 4);
    const uint32_t rowB = (uint32_t)(wn * 32 + ((lane >> 4) << 3) + (lane & 7));
    const uint32_t hiB  = (uint32_t)((lane >> 3) & 1);
    const uint32_t lr   = (uint32_t)((lane >> 1) & 3);

    // --- mainloop: 32 iterations of BK=32 -----------------------------------
    int buf = 0;                                  // kt % 3
    int nbuf = 2;                                 // (kt+2) % 3
#pragma unroll 1
    for (int kt = 0; kt < 32; kt++) {
        CP_WAIT1();                               // own groups: stage kt done
        __syncthreads();                          // ALL warps' stage-kt data visible
                                                  // + all reads of stage (kt+2)%3 done

        const uint32_t base = sbase + buf * STAGE_BYTES;
#pragma unroll
        for (int ks = 0; ks < 2; ks++) {
            const uint32_t kb = (uint32_t)(ks * 2);
            uint32_t bf0[8], bf1[8], af[16];

            const uint32_t offB = rowB * 64 + (((kb + hiB) ^ lr) << 4);
            LDSM4(bf0,     base + 16384 + offB);
            LDSM4(bf0 + 4, base + 16384 + offB + 16 * 64);
            LDSM4(bf1,     base + 24576 + offB);
            LDSM4(bf1 + 4, base + 24576 + offB + 16 * 64);

            const uint32_t offA = rowA * 64 + (((kb + hiA) ^ lr) << 4);
            LDSM4(af,      base + offA);
            LDSM4(af + 4,  base + offA + 16 * 64);
            LDSM4(af + 8,  base + offA + 32 * 64);
            LDSM4(af + 12, base + offA + 48 * 64);

#pragma unroll
            for (int mt = 0; mt < 4; mt++)
#pragma unroll
                for (int nt = 0; nt < 4; nt++)
                    MMA16816(acc[mt][nt], af + mt * 4, bf0 + nt * 2);

            // spread cp.async issue into the MMA stream (after first MMA block)
            if (ks == 0) {
                if (kt < 30) {
                    const uint32_t sb = sbase + nbuf * STAGE_BYTES;
                    const size_t go = (size_t)(kt + 2) * 32 + (size_t)c0 * 8;
#pragma unroll
                    for (int a = 0; a < 4; a++) {
                        cp16(sb + a * 8192 + so0, gsrc[a] + (size_t)r0 * NN + go);
                        cp16(sb + a * 8192 + so1, gsrc[a] + (size_t)(r0 + 64) * NN + go);
                    }
                }
                CP_COMMIT();
            }

#pragma unroll
            for (int mt = 0; mt < 4; mt++)
#pragma unroll
                for (int nt = 0; nt < 4; nt++)
                    MMA16816(acc[mt][nt], af + mt * 4, bf1 + nt * 2);

            // A comp1 (q1 / p1) reuses af registers
            LDSM4(af,      base + 8192 + offA);
            LDSM4(af + 4,  base + 8192 + offA + 16 * 64);
            LDSM4(af + 8,  base + 8192 + offA + 32 * 64);
            LDSM4(af + 12, base + 8192 + offA + 48 * 64);
#pragma unroll
            for (int mt = 0; mt < 4; mt++)
#pragma unroll
                for (int nt = 0; nt < 4; nt++)
                    MMA16816(acc[mt][nt], af + mt * 4, bf0 + nt * 2);
        }

        buf  = (buf  == 2) ? 0 : buf + 1;
        nbuf = (nbuf == 2) ? 0 : nbuf + 1;
    }

    // --- epilogue: direct fp32 stores ---------------------------------------
    const int er = lane >> 2, ec = (lane & 3) * 2;
#pragma unroll
    for (int mt = 0; mt < 4; mt++) {
        const int rr = m0 + wm * 64 + mt * 16 + er;
#pragma unroll
        for (int nt = 0; nt < 4; nt++) {
            const int cc = n0 + wn * 32 + nt * 8 + ec;
            *(float2*)&Cb[(size_t)rr * NN + cc] =
                make_float2(acc[mt][nt][0], acc[mt][nt][1]);
            *(float2*)&Cb[(size_t)(rr + 8) * NN + cc] =
                make_float2(acc[mt][nt][2], acc[mt][nt][3]);
        }
    }
}

// ---------------------------------------------------------------------------
// Row softmax over g_scores; writes 2-term bf16 split of probs to g_p0,g_p1
// ---------------------------------------------------------------------------
__global__ __launch_bounds__(128) void softmax_kernel()
{
    __shared__ float red[4];
    const size_t rowoff = (size_t)blockIdx.x * NN;
    const float* p = g_scores + rowoff;
    const int t = threadIdx.x, lane = t & 31, wid = t >> 5;

    float4 v0 = ((const float4*)p)[t];
    float4 v1 = ((const float4*)p)[t + 128];

    float m = fmaxf(fmaxf(fmaxf(v0.x, v0.y), fmaxf(v0.z, v0.w)),
                    fmaxf(fmaxf(v1.x, v1.y), fmaxf(v1.z, v1.w)));
#pragma unroll
    for (int off = 16; off > 0; off >>= 1)
        m = fmaxf(m, __shfl_xor_sync(0xffffffffu, m, off));
    if (lane == 0) red[wid] = m;
    __syncthreads();
    m = fmaxf(fmaxf(red[0], red[1]), fmaxf(red[2], red[3]));
    __syncthreads();

    v0.x = __expf(v0.x - m); v0.y = __expf(v0.y - m);
    v0.z = __expf(v0.z - m); v0.w = __expf(v0.w - m);
    v1.x = __expf(v1.x - m); v1.y = __expf(v1.y - m);
    v1.z = __expf(v1.z - m); v1.w = __expf(v1.w - m);

    float s = v0.x + v0.y + v0.z + v0.w + v1.x + v1.y + v1.z + v1.w;
#pragma unroll
    for (int off = 16; off > 0; off >>= 1)
        s += __shfl_xor_sync(0xffffffffu, s, off);
    if (lane == 0) red[wid] = s;
    __syncthreads();
    s = red[0] + red[1] + red[2] + red[3];
    const float inv = 1.0f / s;

    float w0[4] = {v0.x * inv, v0.y * inv, v0.z * inv, v0.w * inv};
    float w1[4] = {v1.x * inv, v1.y * inv, v1.z * inv, v1.w * inv};

    __nv_bfloat16 a0[4], a1[4], b0[4], b1[4];
#pragma unroll
    for (int j = 0; j < 4; j++) {
        a0[j] = __float2bfloat16(w0[j]);
        a1[j] = __float2bfloat16(w0[j] - __bfloat162float(a0[j]));
        b0[j] = __float2bfloat16(w1[j]);
        b1[j] = __float2bfloat16(w1[j] - __bfloat162float(b0[j]));
    }
    *(uint2*)(g_p0 + rowoff + t * 4)       = *(const uint2*)a0;
    *(uint2*)(g_p1 + rowoff + t * 4)       = *(const uint2*)a1;
    *(uint2*)(g_p0 + rowoff + 512 + t * 4) = *(const uint2*)b0;
    *(uint2*)(g_p1 + rowoff + 512 + t * 4) = *(const uint2*)b1;
}

// ---------------------------------------------------------------------------
// Entry point
// ---------------------------------------------------------------------------
extern "C" void kernel_launch(void* const* d_in, const int* in_sizes, int n_in,
                              void* d_out, int out_size)
{
    const float* Q = (const float*)d_in[0];   // decoder_hidden  [16,1024,1024]
    const float* E = (const float*)d_in[1];   // encoder_outputs [16,1024,1024]
    float* O = (float*)d_out;                 // context         [16,1024,1024]

    cudaFuncSetAttribute(gemm_kernel, cudaFuncAttributeMaxDynamicSharedMemorySize,
                         GEMM_SMEM);

    split_kernel<<<dim3(16, 16, 32), 256>>>(Q, E);    // Q split + E split/transpose

    dim3 grd(NN / 128, NN / 128, NB);                             // (8,8,16)
    gemm_kernel<<<grd, 256, GEMM_SMEM>>>(nullptr, 0);             // S = Q·E^T
    softmax_kernel<<<NB * NN, 128>>>();                           // P + bf16 split
    gemm_kernel<<<grd, 256, GEMM_SMEM>>>(O, 1);                   // O = P·E
}